// round 17
// baseline (speedup 1.0000x reference)
#include <cuda_runtime.h>
#include <cuda_bf16.h>
#include <stdint.h>
#include <math.h>

// Problem shape (fixed by dataset)
static constexpr int Bb = 4;
static constexpr int Ss = 2048;
static constexpr int Ee = 1024;
static constexpr int Dd = 1024;

// ---------------- scratch (proven 163 MB budget) ----------------
__device__ float g_q[(size_t)Bb * Ss * Dd];   // 32 MB; reused as V^T after scores
__device__ float g_k[(size_t)Bb * Ss * Dd];   // 32 MB
__device__ float g_v[(size_t)Bb * Ss * Dd];   // 32 MB
__device__ float g_p[(size_t)Bb * Ss * Ss];   // 67 MB

// ---------------- common helpers ----------------
__device__ __forceinline__ uint32_t smem_u32(const void* p) {
    uint32_t a;
    asm("{ .reg .u64 t; cvta.to.shared.u64 t, %1; cvt.u32.u64 %0, t; }" : "=r"(a) : "l"(p));
    return a;
}
#define SW64(o) ((o) ^ (((o) >> 3) & 0x30))

__device__ __forceinline__ void ldsm4(uint32_t* r, uint32_t a) {
    asm volatile("ldmatrix.sync.aligned.m8n8.x4.shared.b16 {%0,%1,%2,%3}, [%4];"
        : "=r"(r[0]), "=r"(r[1]), "=r"(r[2]), "=r"(r[3]) : "r"(a));
}
__device__ __forceinline__ void mma_bf16(float* d, const uint32_t* a,
                                         uint32_t b0, uint32_t b1) {
    asm volatile("mma.sync.aligned.m16n8k16.row.col.f32.bf16.bf16.f32 "
        "{%0,%1,%2,%3}, {%4,%5,%6,%7}, {%8,%9}, {%0,%1,%2,%3};"
        : "+f"(d[0]), "+f"(d[1]), "+f"(d[2]), "+f"(d[3])
        : "r"(a[0]), "r"(a[1]), "r"(a[2]), "r"(a[3]), "r"(b0), "r"(b1));
}

// mma smem planes inside the shared 32KB buffer
static constexpr int SM_AH = 0;
static constexpr int SM_AL = 8192;
static constexpr int SM_BH = 16384;
static constexpr int SM_BL = 24576;

__device__ __forceinline__ void cvt8(const float4 u, const float4 v,
                                     uint4& hi, uint4& lo) {
    float f[8] = {u.x, u.y, u.z, u.w, v.x, v.y, v.z, v.w};
    uint32_t hw[4], lw[4];
    #pragma unroll
    for (int p = 0; p < 4; p++) {
        __nv_bfloat16 h0 = __float2bfloat16(f[2 * p]);
        __nv_bfloat16 h1 = __float2bfloat16(f[2 * p + 1]);
        float l0 = f[2 * p]     - __bfloat162float(h0);
        float l1 = f[2 * p + 1] - __bfloat162float(h1);
        __nv_bfloat162 hh = __halves2bfloat162(h0, h1);
        __nv_bfloat162 ll = __halves2bfloat162(__float2bfloat16(l0), __float2bfloat16(l1));
        hw[p] = *(uint32_t*)&hh;
        lw[p] = *(uint32_t*)&ll;
    }
    hi = make_uint4(hw[0], hw[1], hw[2], hw[3]);
    lo = make_uint4(lw[0], lw[1], lw[2], lw[3]);
}

// ---------------- mma core (split-bf16, no prefetch regs -> no spills) --------
// C(128x128) = A(128xK) * B(128xK)^T; fp32 in global, on-the-fly hi/lo planes.
__device__ __forceinline__ void mma_core(char* smem,
    const float* __restrict__ A, long ldA, const float* __restrict__ B, long ldB,
    float* C, long ldC, int m0, int n0, int nchunks)
{
    uint32_t sb = smem_u32(smem);
    int tid = threadIdx.x, lane = tid & 31, wid = tid >> 5;
    int wm = (wid & 3) * 32, wn = (wid >> 2) * 64;
    int r8 = lane & 7, sel = lane >> 3;

    int arb0 = (wm + (sel & 1) * 8 + r8) * 64 + (sel >> 1) * 16;
    int arb1 = arb0 + 16 * 64;
    int brb[4];
    #pragma unroll
    for (int j = 0; j < 4; j++)
        brb[j] = (wn + j * 16 + (sel & 1) * 8 + r8) * 64 + (sel >> 1) * 16;

    int lrow = tid >> 1, lkh = (tid & 1) * 16;
    const float* ap = A + (size_t)lrow * ldA + lkh;
    const float* bp = B + (size_t)lrow * ldB + lkh;
    int sa0 = SW64(lrow * 64 + lkh * 2);
    int sa1 = SW64(lrow * 64 + lkh * 2 + 16);

    float acc[2][8][4] = {};

    for (int c = 0; c < nchunks; c++) {
        long co = (long)c * 32;
        {
            float4 a0 = *(const float4*)(ap + co);
            float4 a1 = *(const float4*)(ap + co + 4);
            float4 a2 = *(const float4*)(ap + co + 8);
            float4 a3 = *(const float4*)(ap + co + 12);
            float4 b0 = *(const float4*)(bp + co);
            float4 b1 = *(const float4*)(bp + co + 4);
            float4 b2 = *(const float4*)(bp + co + 8);
            float4 b3 = *(const float4*)(bp + co + 12);
            uint4 hi, lo;
            cvt8(a0, a1, hi, lo);
            *(uint4*)(smem + SM_AH + sa0) = hi;
            *(uint4*)(smem + SM_AL + sa0) = lo;
            cvt8(a2, a3, hi, lo);
            *(uint4*)(smem + SM_AH + sa1) = hi;
            *(uint4*)(smem + SM_AL + sa1) = lo;
            cvt8(b0, b1, hi, lo);
            *(uint4*)(smem + SM_BH + sa0) = hi;
            *(uint4*)(smem + SM_BL + sa0) = lo;
            cvt8(b2, b3, hi, lo);
            *(uint4*)(smem + SM_BH + sa1) = hi;
            *(uint4*)(smem + SM_BL + sa1) = lo;
        }
        __syncthreads();

        #pragma unroll
        for (int ks = 0; ks < 2; ks++) {
            int kb = ks * 32;
            uint32_t ah0[4], ah1[4], al0[4], al1[4];
            ldsm4(ah0, sb + SM_AH + SW64(arb0 + kb));
            ldsm4(ah1, sb + SM_AH + SW64(arb1 + kb));
            ldsm4(al0, sb + SM_AL + SW64(arb0 + kb));
            ldsm4(al1, sb + SM_AL + SW64(arb1 + kb));
            #pragma unroll
            for (int j = 0; j < 4; j++) {
                uint32_t bh[4], bl[4];
                ldsm4(bh, sb + SM_BH + SW64(brb[j] + kb));
                ldsm4(bl, sb + SM_BL + SW64(brb[j] + kb));
                mma_bf16(acc[0][2 * j],     ah0, bh[0], bh[2]);
                mma_bf16(acc[0][2 * j + 1], ah0, bh[1], bh[3]);
                mma_bf16(acc[1][2 * j],     ah1, bh[0], bh[2]);
                mma_bf16(acc[1][2 * j + 1], ah1, bh[1], bh[3]);
                mma_bf16(acc[0][2 * j],     ah0, bl[0], bl[2]);
                mma_bf16(acc[0][2 * j + 1], ah0, bl[1], bl[3]);
                mma_bf16(acc[1][2 * j],     ah1, bl[0], bl[2]);
                mma_bf16(acc[1][2 * j + 1], ah1, bl[1], bl[3]);
                mma_bf16(acc[0][2 * j],     al0, bh[0], bh[2]);
                mma_bf16(acc[0][2 * j + 1], al0, bh[1], bh[3]);
                mma_bf16(acc[1][2 * j],     al1, bh[0], bh[2]);
                mma_bf16(acc[1][2 * j + 1], al1, bh[1], bh[3]);
            }
        }
        __syncthreads();
    }

    int rbase = m0 + wm + (lane >> 2);
    int cbase = n0 + wn + (lane & 3) * 2;
    #pragma unroll
    for (int i = 0; i < 2; i++)
        #pragma unroll
        for (int jn = 0; jn < 8; jn++)
            #pragma unroll
            for (int h = 0; h < 2; h++) {
                int row = rbase + i * 16 + h * 8;
                int col = cbase + jn * 8;
                *(float2*)(C + (size_t)row * ldC + col) =
                    make_float2(acc[i][jn][h * 2], acc[i][jn][h * 2 + 1]);
            }
}

// ---------------- ffma core (R5-proven fp32 NT, double-buffered) --------------
__device__ __forceinline__ void ffma_core(char* smraw,
    const float* __restrict__ A, long ldA, const float* __restrict__ B, long ldB,
    float* C, long ldC, int m0, int n0, int niter)   // niter = K/16
{
    typedef float (*TileP)[16][128];
    TileP As = (TileP)smraw;               // [2][16][128] = 16 KB
    TileP Bs = (TileP)(smraw + 16384);     // [2][16][128]

    int tid = threadIdx.x;
    int tr = (tid >> 4) * 8, tc = (tid & 15) * 8;
    int lrow = tid >> 2, lc4 = (tid & 3) * 4;

    const float* Ab = A + (size_t)lrow * ldA + lc4;
    const float* Bt = B + (size_t)lrow * ldB + lc4;

    float4 pa0 = *(const float4*)(Ab);
    float4 pa1 = *(const float4*)(Ab + (size_t)64 * ldA);
    float4 pb0 = *(const float4*)(Bt);
    float4 pb1 = *(const float4*)(Bt + (size_t)64 * ldB);

    As[0][lc4 + 0][lrow] = pa0.x; As[0][lc4 + 1][lrow] = pa0.y;
    As[0][lc4 + 2][lrow] = pa0.z; As[0][lc4 + 3][lrow] = pa0.w;
    As[0][lc4 + 0][lrow + 64] = pa1.x; As[0][lc4 + 1][lrow + 64] = pa1.y;
    As[0][lc4 + 2][lrow + 64] = pa1.z; As[0][lc4 + 3][lrow + 64] = pa1.w;
    Bs[0][lc4 + 0][lrow] = pb0.x; Bs[0][lc4 + 1][lrow] = pb0.y;
    Bs[0][lc4 + 2][lrow] = pb0.z; Bs[0][lc4 + 3][lrow] = pb0.w;
    Bs[0][lc4 + 0][lrow + 64] = pb1.x; Bs[0][lc4 + 1][lrow + 64] = pb1.y;
    Bs[0][lc4 + 2][lrow + 64] = pb1.z; Bs[0][lc4 + 3][lrow + 64] = pb1.w;
    __syncthreads();

    float acc[8][8] = {};
    int buf = 0;
    for (int it = 0; it < niter; ++it) {
        if (it + 1 < niter) {
            int k0n = (it + 1) * 16;
            pa0 = *(const float4*)(Ab + k0n);
            pa1 = *(const float4*)(Ab + (size_t)64 * ldA + k0n);
            pb0 = *(const float4*)(Bt + k0n);
            pb1 = *(const float4*)(Bt + (size_t)64 * ldB + k0n);
        }
        #pragma unroll
        for (int kk = 0; kk < 16; kk++) {
            float4 a0 = *(const float4*)&As[buf][kk][tr];
            float4 a1 = *(const float4*)&As[buf][kk][tr + 4];
            float4 b0 = *(const float4*)&Bs[buf][kk][tc];
            float4 b1 = *(const float4*)&Bs[buf][kk][tc + 4];
            float ra[8] = {a0.x, a0.y, a0.z, a0.w, a1.x, a1.y, a1.z, a1.w};
            float rb[8] = {b0.x, b0.y, b0.z, b0.w, b1.x, b1.y, b1.z, b1.w};
            #pragma unroll
            for (int i = 0; i < 8; i++)
                #pragma unroll
                for (int j = 0; j < 8; j++)
                    acc[i][j] += ra[i] * rb[j];
        }
        if (it + 1 < niter) {
            int nb = buf ^ 1;
            As[nb][lc4 + 0][lrow] = pa0.x; As[nb][lc4 + 1][lrow] = pa0.y;
            As[nb][lc4 + 2][lrow] = pa0.z; As[nb][lc4 + 3][lrow] = pa0.w;
            As[nb][lc4 + 0][lrow + 64] = pa1.x; As[nb][lc4 + 1][lrow + 64] = pa1.y;
            As[nb][lc4 + 2][lrow + 64] = pa1.z; As[nb][lc4 + 3][lrow + 64] = pa1.w;
            Bs[nb][lc4 + 0][lrow] = pb0.x; Bs[nb][lc4 + 1][lrow] = pb0.y;
            Bs[nb][lc4 + 2][lrow] = pb0.z; Bs[nb][lc4 + 3][lrow] = pb0.w;
            Bs[nb][lc4 + 0][lrow + 64] = pb1.x; Bs[nb][lc4 + 1][lrow + 64] = pb1.y;
            Bs[nb][lc4 + 2][lrow + 64] = pb1.z; Bs[nb][lc4 + 3][lrow + 64] = pb1.w;
            __syncthreads();
            buf = nb;
        }
    }

    #pragma unroll
    for (int i = 0; i < 8; i++) {
        float* crow = C + (size_t)(m0 + tr + i) * ldC + n0 + tc;
        *(float4*)(crow)     = make_float4(acc[i][0], acc[i][1], acc[i][2], acc[i][3]);
        *(float4*)(crow + 4) = make_float4(acc[i][4], acc[i][5], acc[i][6], acc[i][7]);
    }
}

// Hybrid dispatch: (flat>>2)&1 flips between bids b and b+148 (148=4*37),
// so wave-1 SM pairs get one FFMA CTA + one MMA CTA -> both pipes busy.
__device__ __forceinline__ bool use_ffma(int flat) { return ((flat >> 2) & 1) != 0; }

// ---------------- kernels ----------------

__global__ void __launch_bounds__(256, 2) proj_h(
    const float* __restrict__ x,
    const float* __restrict__ wq, const float* __restrict__ wk,
    const float* __restrict__ wv)
{
    __shared__ __align__(128) char smem[32768];
    int bx = blockIdx.x, by = blockIdx.y, bz = blockIdx.z;
    int flat = bx + 8 * (by + 64 * bz);
    const float* W = (bz == 0) ? wq : (bz == 1) ? wk : wv;
    float* C = (bz == 0) ? g_q : (bz == 1) ? g_k : g_v;
    const float* A = x + (size_t)(by * 128) * Ee;
    const float* B = W + (size_t)(bx * 128) * Ee;

    if (use_ffma(flat))
        ffma_core(smem, A, Ee, B, Ee, C, Dd, by * 128, bx * 128, Ee / 16);
    else
        mma_core(smem, A, Ee, B, Ee, C, Dd, by * 128, bx * 128, Ee / 32);
}

__global__ void __launch_bounds__(256, 2) scores_h()
{
    int bx = blockIdx.x, by = blockIdx.y, bz = blockIdx.z;
    if (bx > by) return;
    __shared__ __align__(128) char smem[32768];
    int flat = bx + 16 * (by + 16 * bz);

    const float* A = g_q + (size_t)bz * Ss * Dd + (size_t)(by * 128) * Dd;
    const float* B = g_k + (size_t)bz * Ss * Dd + (size_t)(bx * 128) * Dd;
    float* C = g_p + (size_t)bz * Ss * Ss;

    if (use_ffma(flat))
        ffma_core(smem, A, Dd, B, Dd, C, Ss, by * 128, bx * 128, Dd / 16);
    else
        mma_core(smem, A, Dd, B, Dd, C, Ss, by * 128, bx * 128, Dd / 32);
}

// V [t,d] -> V^T [d,t] fp32 into g_q (dead after scores). grid (32, 64, 4).
__global__ void __launch_bounds__(256) transpose_v()
{
    __shared__ float t[32][33];
    int bz = blockIdx.z;
    const float* src = g_v + (size_t)bz * Ss * Dd;
    float* dst = g_q + (size_t)bz * Dd * Ss;
    int d0 = blockIdx.x * 32, t0 = blockIdx.y * 32;
    int tx = threadIdx.x & 31, ty = threadIdx.x >> 5;

    #pragma unroll
    for (int p = 0; p < 4; p++)
        t[ty + p * 8][tx] = src[(size_t)(t0 + ty + p * 8) * Dd + d0 + tx];
    __syncthreads();
    #pragma unroll
    for (int p = 0; p < 4; p++)
        dst[(size_t)(d0 + ty + p * 8) * Ss + t0 + tx] = t[tx][ty + p * 8];
}

__global__ void __launch_bounds__(256) softmax_causal()
{
    const int S = Ss;
    int row = blockIdx.x;
    int b = row >> 11, s = row & (S - 1);
    float* p = g_p + (size_t)b * S * S + (size_t)s * S;
    int L = s + 1;
    const float scale = 0.03125f;
    int tid = threadIdx.x;

    __shared__ float red[8];

    float m = -1e30f;
    for (int i = tid; i < L; i += 256) m = fmaxf(m, p[i]);
    #pragma unroll
    for (int o = 16; o; o >>= 1) m = fmaxf(m, __shfl_xor_sync(0xFFFFFFFFu, m, o));
    if ((tid & 31) == 0) red[tid >> 5] = m;
    __syncthreads();
    if (tid == 0) {
        float mm = red[0];
        #pragma unroll
        for (int i = 1; i < 8; i++) mm = fmaxf(mm, red[i]);
        red[0] = mm;
    }
    __syncthreads();
    m = red[0] * scale;
    __syncthreads();

    float sum = 0.f;
    for (int i = tid; i < L; i += 256) sum += __expf(p[i] * scale - m);
    #pragma unroll
    for (int o = 16; o; o >>= 1) sum += __shfl_xor_sync(0xFFFFFFFFu, sum, o);
    if ((tid & 31) == 0) red[tid >> 5] = sum;
    __syncthreads();
    if (tid == 0) {
        float ss = 0.f;
        #pragma unroll
        for (int i = 0; i < 8; i++) ss += red[i];
        red[0] = ss;
    }
    __syncthreads();
    float inv = 1.0f / red[0];

    for (int i = tid; i < S; i += 256)
        p[i] = (i < L) ? __expf(p[i] * scale - m) * inv : 0.0f;
}

__global__ void __launch_bounds__(256, 2) av_h(float* __restrict__ out)
{
    int bx = blockIdx.x, by = blockIdx.y, bz = blockIdx.z;
    __shared__ __align__(128) char smem[32768];
    int flat = bx + 8 * (by + 16 * bz);

    const float* A = g_p + (size_t)bz * Ss * Ss + (size_t)(by * 128) * Ss;
    const float* B = g_q + (size_t)bz * Dd * Ss + (size_t)(bx * 128) * Ss; // V^T
    float* C = out + (size_t)bz * Ss * Dd;

    if (use_ffma(flat))
        ffma_core(smem, A, Ss, B, Ss, C, Dd, by * 128, bx * 128, (by + 1) * 8);
    else
        mma_core(smem, A, Ss, B, Ss, C, Dd, by * 128, bx * 128, (by + 1) * 4);
}

// ---------------- launch ----------------
extern "C" void kernel_launch(void* const* d_in, const int* in_sizes, int n_in,
                              void* d_out, int out_size)
{
    const float* x  = (const float*)d_in[0];
    const float* wq = (const float*)d_in[1];
    const float* wk = (const float*)d_in[2];
    const float* wv = (const float*)d_in[3];
    float* out = (float*)d_out;

    dim3 blk(256);

    proj_h<<<dim3(Dd / 128, (Bb * Ss) / 128, 3), blk>>>(x, wq, wk, wv);
    scores_h<<<dim3(Ss / 128, Ss / 128, Bb), blk>>>();
    transpose_v<<<dim3(Dd / 32, Ss / 32, Bb), blk>>>();   // g_q := V^T (q dead)
    softmax_causal<<<Bb * Ss, blk>>>();
    av_h<<<dim3(Dd / 128, Ss / 128, Bb), blk>>>(out);
}